// round 6
// baseline (speedup 1.0000x reference)
#include <cuda_runtime.h>
#include <cuda_bf16.h>
#include <math.h>

#define N_NODES 50000
#define N_EDGES 1600000
#define N_GRAPHS 2048
#define DIM 133
#define EPS 1e-5f

// ---------------- scratch (device globals; no allocation allowed) ----------------
__device__ float g_h[(size_t)N_NODES * DIM];   // GEMM output (pre-aggregation)
__device__ float g_t[(size_t)N_NODES * DIM];   // layer output (post BN) / GEMM2 input
__device__ int   g_cnt[N_NODES];               // in-degree histogram (no self loop)
__device__ int   g_off[N_NODES];               // CSR row offsets (exclusive scan)
__device__ int   g_cursor[N_NODES];            // scatter cursors
__device__ int   g_src[N_EDGES];               // CSR: source node per (dest-sorted) edge
__device__ float g_dinv[N_NODES];              // rsqrt(deg) with self loop
__device__ float g_gcnt[N_GRAPHS];             // nodes per graph

// ---------------- preprocessing ----------------
__global__ void zero_cnt_kernel() {
    int i = blockIdx.x * blockDim.x + threadIdx.x;
    if (i < N_NODES) g_cnt[i] = 0;
}

__global__ void hist_kernel(const int* __restrict__ col) {
    for (int e = blockIdx.x * blockDim.x + threadIdx.x; e < N_EDGES;
         e += gridDim.x * blockDim.x) {
        atomicAdd(&g_cnt[col[e]], 1);
    }
}

// single-block exclusive scan over 50000 ints + dinv computation
__global__ void scan_kernel() {
    __shared__ int wsum[32];
    __shared__ int carry_s;
    __shared__ int tile_total;
    int tid = threadIdx.x;
    int lane = tid & 31, wid = tid >> 5;
    if (tid == 0) carry_s = 0;
    __syncthreads();
    for (int base = 0; base < N_NODES; base += 1024) {
        int i = base + tid;
        int v = (i < N_NODES) ? g_cnt[i] : 0;
        // warp inclusive scan
        int s = v;
        #pragma unroll
        for (int d = 1; d < 32; d <<= 1) {
            int t = __shfl_up_sync(0xFFFFFFFFu, s, d);
            if (lane >= d) s += t;
        }
        if (lane == 31) wsum[wid] = s;
        __syncthreads();
        if (wid == 0) {
            int w = wsum[lane];
            int ws = w;
            #pragma unroll
            for (int d = 1; d < 32; d <<= 1) {
                int t = __shfl_up_sync(0xFFFFFFFFu, ws, d);
                if (lane >= d) ws += t;
            }
            wsum[lane] = ws - w;           // exclusive warp offset
            if (lane == 31) tile_total = ws;
        }
        __syncthreads();
        int excl = carry_s + wsum[wid] + (s - v);
        if (i < N_NODES) {
            g_off[i] = excl;
            g_cursor[i] = excl;
            g_dinv[i] = rsqrtf((float)(v + 1));   // +1 self loop
        }
        __syncthreads();
        if (tid == 0) carry_s += tile_total;
        __syncthreads();
    }
}

__global__ void scatter_kernel(const int* __restrict__ row,
                               const int* __restrict__ col) {
    for (int e = blockIdx.x * blockDim.x + threadIdx.x; e < N_EDGES;
         e += gridDim.x * blockDim.x) {
        int c = col[e];
        int p = atomicAdd(&g_cursor[c], 1);
        g_src[p] = row[e];
    }
}

// ---------------- GEMM: g_h[M,133] = A[M,133] @ W[133,133] ----------------
// use_gt != 0 -> A comes from the device-global g_t (layer 2); otherwise A_ext.
#define BM 64
__global__ __launch_bounds__(256) void gemm_kernel(const float* __restrict__ A_ext,
                                                   const float* __restrict__ W,
                                                   int use_gt) {
    __shared__ float xs[BM * 19];
    __shared__ float ws[19 * 136];
    const float* __restrict__ A = use_gt ? (const float*)g_t : A_ext;
    int tid = threadIdx.x;
    int row0 = blockIdx.x * BM;
    int r = tid >> 2;       // 0..63
    int c0 = tid & 3;       // 0..3
    float acc[34];
    #pragma unroll
    for (int j = 0; j < 34; j++) acc[j] = 0.f;

    for (int kt = 0; kt < 7; kt++) {        // 7 * 19 = 133
        int k0 = kt * 19;
        for (int idx = tid; idx < BM * 19; idx += 256) {
            int rr = idx / 19, kk = idx - rr * 19;
            int grow = row0 + rr;
            xs[idx] = (grow < N_NODES) ? A[(size_t)grow * DIM + k0 + kk] : 0.f;
        }
        for (int idx = tid; idx < 19 * DIM; idx += 256) {
            int kk = idx / DIM, cc = idx - kk * DIM;
            ws[kk * 136 + cc] = W[(k0 + kk) * DIM + cc];
        }
        __syncthreads();
        #pragma unroll
        for (int k = 0; k < 19; k++) {
            float xv = xs[r * 19 + k];
            #pragma unroll
            for (int j = 0; j < 34; j++) {
                int c = c0 + 4 * j;
                if (c < DIM) acc[j] = fmaf(xv, ws[k * 136 + c], acc[j]);
            }
        }
        __syncthreads();
    }
    int grow = row0 + r;
    if (grow < N_NODES) {
        #pragma unroll
        for (int j = 0; j < 34; j++) {
            int c = c0 + 4 * j;
            if (c < DIM) g_h[(size_t)grow * DIM + c] = acc[j];
        }
    }
}

// -------- aggregation: g_t = BN(relu(scatter(norm * g_h[src]) + b)) -----------
// one warp per destination node; zero atomics (CSR by destination)
__global__ __launch_bounds__(256) void agg_kernel(const float* __restrict__ b,
                                                  const float* __restrict__ gam,
                                                  const float* __restrict__ bet,
                                                  const float* __restrict__ rm,
                                                  const float* __restrict__ rv) {
    int warp = (blockIdx.x * blockDim.x + threadIdx.x) >> 5;
    int lane = threadIdx.x & 31;
    if (warp >= N_NODES) return;
    int node = warp;
    const float* __restrict__ h = (const float*)g_h;

    float di = g_dinv[node];
    int start = g_off[node];
    int end = (node + 1 < N_NODES) ? g_off[node + 1] : N_EDGES;

    float acc[5];
    float sw = di * di;   // self-loop weight
    const float* hn = h + (size_t)node * DIM;
    #pragma unroll
    for (int m = 0; m < 5; m++) {
        int d = lane + 32 * m;
        acc[m] = (d < DIM) ? sw * hn[d] : 0.f;
    }

    for (int j = start; j < end; j += 32) {
        int jj = j + lane;
        int rr = 0;
        float wv = 0.f;
        if (jj < end) {
            rr = g_src[jj];
            wv = g_dinv[rr];
        }
        int cnt = min(32, end - j);
        for (int l = 0; l < cnt; l++) {
            int src = __shfl_sync(0xFFFFFFFFu, rr, l);
            float w = __shfl_sync(0xFFFFFFFFu, wv, l) * di;
            const float* hr = h + (size_t)src * DIM;
            #pragma unroll
            for (int m = 0; m < 5; m++) {
                int d = lane + 32 * m;
                if (d < DIM) acc[m] = fmaf(w, hr[d], acc[m]);
            }
        }
    }

    #pragma unroll
    for (int m = 0; m < 5; m++) {
        int d = lane + 32 * m;
        if (d < DIM) {
            float v = acc[m] + b[d];
            v = fmaxf(v, 0.f);                       // ReLU
            v = (v - rm[d]) * rsqrtf(rv[d] + EPS) * gam[d] + bet[d];  // BN eval
            g_t[(size_t)node * DIM + d] = v;
        }
    }
}

// ---------------- pooling ----------------
__global__ void zero_pool_kernel(float* __restrict__ out) {
    int i = blockIdx.x * blockDim.x + threadIdx.x;
    int total = N_GRAPHS * DIM;
    if (i < total) out[i] = 0.f;
    if (i < N_GRAPHS) g_gcnt[i] = 0.f;
}

__global__ void pool_sum_kernel(const int* __restrict__ batch,
                                float* __restrict__ out) {
    for (int i = blockIdx.x * blockDim.x + threadIdx.x; i < N_NODES * DIM;
         i += gridDim.x * blockDim.x) {
        int n = i / DIM;
        int d = i - n * DIM;
        int g = batch[n];
        atomicAdd(&out[g * DIM + d], g_t[i]);
        if (d == 0) atomicAdd(&g_gcnt[g], 1.f);
    }
}

__global__ void pool_div_kernel(float* __restrict__ out) {
    int i = blockIdx.x * blockDim.x + threadIdx.x;
    if (i < N_GRAPHS * DIM) {
        int g = i / DIM;
        out[i] *= 1.f / fmaxf(g_gcnt[g], 1.f);
    }
}

// ---------------- launch ----------------
extern "C" void kernel_launch(void* const* d_in, const int* in_sizes, int n_in,
                              void* d_out, int out_size) {
    const float* x     = (const float*)d_in[0];
    const int*   ei    = (const int*)d_in[1];   // [2, E] int32 (JAX x64 disabled)
    const int*   batch = (const int*)d_in[2];   // [N] int32
    const float* W1 = (const float*)d_in[3];
    const float* b1 = (const float*)d_in[4];
    const float* W2 = (const float*)d_in[5];
    const float* b2 = (const float*)d_in[6];
    const float* g1 = (const float*)d_in[7];
    const float* be1 = (const float*)d_in[8];
    const float* rm1 = (const float*)d_in[9];
    const float* rv1 = (const float*)d_in[10];
    const float* g2 = (const float*)d_in[11];
    const float* be2 = (const float*)d_in[12];
    const float* rm2 = (const float*)d_in[13];
    const float* rv2 = (const float*)d_in[14];
    float* out = (float*)d_out;

    const int* row = ei;            // first E entries
    const int* col = ei + N_EDGES;  // second E entries

    // 1. CSR build
    zero_cnt_kernel<<<(N_NODES + 255) / 256, 256>>>();
    hist_kernel<<<2048, 256>>>(col);
    scan_kernel<<<1, 1024>>>();
    scatter_kernel<<<2048, 256>>>(row, col);

    // 2. layer 1: GEMM -> aggregate (+bias, ReLU, BN fused)
    gemm_kernel<<<(N_NODES + BM - 1) / BM, 256>>>(x, W1, 0);
    agg_kernel<<<(N_NODES * 32 + 255) / 256, 256>>>(b1, g1, be1, rm1, rv1);

    // 3. layer 2 (A comes from g_t via flag)
    gemm_kernel<<<(N_NODES + BM - 1) / BM, 256>>>(x, W2, 1);
    agg_kernel<<<(N_NODES * 32 + 255) / 256, 256>>>(b2, g2, be2, rm2, rv2);

    // 4. global mean pool
    zero_pool_kernel<<<(N_GRAPHS * DIM + 255) / 256, 256>>>(out);
    pool_sum_kernel<<<4096, 256>>>(batch, out);
    pool_div_kernel<<<(N_GRAPHS * DIM + 255) / 256, 256>>>(out);
}

// round 7
// speedup vs baseline: 1.7140x; 1.7140x over previous
#include <cuda_runtime.h>
#include <cuda_bf16.h>
#include <math.h>

#define N_NODES 50000
#define N_EDGES 1600000
#define N_GRAPHS 2048
#define DIM 133
#define EPS 1e-5f
#define NB 196           // ceil(50000/256)
#define WSTRIDE 136      // padded W tile stride (133 -> 136)
#define KSTEPS 17        // 17*8 = 136 >= 133
#define NTILES 17        // 17*8 = 136 >= 133

// ---------------- scratch (device globals; no allocation allowed) ----------------
__device__ float g_h[(size_t)N_NODES * DIM];   // GEMM output (pre-aggregation)
__device__ float g_t[(size_t)N_NODES * DIM];   // layer output (post BN) / GEMM2 input
__device__ int   g_cnt[N_NODES];               // in-degree histogram (no self loop)
__device__ int   g_off[N_NODES];               // CSR row offsets (exclusive scan)
__device__ int   g_cursor[N_NODES];            // scatter cursors
__device__ int   g_src[N_EDGES];               // CSR: source node per (dest-sorted) edge
__device__ float g_dinv[N_NODES];              // rsqrt(deg) with self loop
__device__ int   g_bsum[NB];                   // per-block histogram sums
__device__ int   g_boff[NB];                   // per-block exclusive offsets
__device__ int   g_goff[N_GRAPHS + 1];         // per-graph node ranges (batch sorted)

// ---------------- preprocessing ----------------
__global__ void zero_cnt_kernel() {
    int i = blockIdx.x * blockDim.x + threadIdx.x;
    if (i < N_NODES) g_cnt[i] = 0;
}

__global__ void hist_kernel(const int* __restrict__ col) {
    for (int e = blockIdx.x * blockDim.x + threadIdx.x; e < N_EDGES;
         e += gridDim.x * blockDim.x) {
        atomicAdd(&g_cnt[col[e]], 1);
    }
}

// phase 1: per-block reduction of g_cnt
__global__ __launch_bounds__(256) void reduce_kernel() {
    int i = blockIdx.x * 256 + threadIdx.x;
    int v = (i < N_NODES) ? g_cnt[i] : 0;
    #pragma unroll
    for (int off = 16; off > 0; off >>= 1)
        v += __shfl_down_sync(0xFFFFFFFFu, v, off);
    __shared__ int ws[8];
    int lane = threadIdx.x & 31, w = threadIdx.x >> 5;
    if (lane == 0) ws[w] = v;
    __syncthreads();
    if (threadIdx.x == 0) {
        int s = 0;
        #pragma unroll
        for (int j = 0; j < 8; j++) s += ws[j];
        g_bsum[blockIdx.x] = s;
    }
}

// phase 2: one warp scans the 196 block sums (exclusive)
__global__ void scan_bsum_kernel() {
    int lane = threadIdx.x;
    int carry = 0;
    for (int base = 0; base < NB; base += 32) {
        int i = base + lane;
        int v = (i < NB) ? g_bsum[i] : 0;
        int s = v;
        #pragma unroll
        for (int d = 1; d < 32; d <<= 1) {
            int t = __shfl_up_sync(0xFFFFFFFFu, s, d);
            if (lane >= d) s += t;
        }
        if (i < NB) g_boff[i] = carry + s - v;
        carry += __shfl_sync(0xFFFFFFFFu, s, 31);
    }
}

// phase 3: block-local scan + global offset; also writes dinv
__global__ __launch_bounds__(256) void scan_apply_kernel() {
    int i = blockIdx.x * 256 + threadIdx.x;
    int lane = threadIdx.x & 31, w = threadIdx.x >> 5;
    int v = (i < N_NODES) ? g_cnt[i] : 0;
    int s = v;
    #pragma unroll
    for (int d = 1; d < 32; d <<= 1) {
        int t = __shfl_up_sync(0xFFFFFFFFu, s, d);
        if (lane >= d) s += t;
    }
    __shared__ int ws[8];
    __shared__ int wo[8];
    if (lane == 31) ws[w] = s;
    __syncthreads();
    if (threadIdx.x == 0) {
        int r = 0;
        #pragma unroll
        for (int j = 0; j < 8; j++) { wo[j] = r; r += ws[j]; }
    }
    __syncthreads();
    if (i < N_NODES) {
        int excl = g_boff[blockIdx.x] + wo[w] + (s - v);
        g_off[i] = excl;
        g_cursor[i] = excl;
        g_dinv[i] = rsqrtf((float)(v + 1));   // +1 self loop
    }
}

__global__ void scatter_kernel(const int* __restrict__ row,
                               const int* __restrict__ col) {
    for (int e = blockIdx.x * blockDim.x + threadIdx.x; e < N_EDGES;
         e += gridDim.x * blockDim.x) {
        int c = col[e];
        int p = atomicAdd(&g_cursor[c], 1);
        g_src[p] = row[e];
    }
}

// per-graph node ranges from the SORTED batch array
__global__ void goff_kernel(const int* __restrict__ batch) {
    int i = blockIdx.x * blockDim.x + threadIdx.x;
    if (i >= N_NODES) return;
    int b = batch[i];
    int prev = (i == 0) ? -1 : batch[i - 1];
    for (int g = prev + 1; g <= b; g++) g_goff[g] = i;
    if (i == N_NODES - 1) {
        for (int g = b + 1; g <= N_GRAPHS; g++) g_goff[g] = N_NODES;
    }
}

// ---------- tf32 tensor-core GEMM: g_h[M,133] = A[M,133] @ W[133,133] ----------
// 128 threads (4 warps), 64 rows per block, warp handles 16 rows.
// W staged in dynamic SMEM pre-converted to tf32 (136x136, zero padded).
// A fragments loaded straight from GMEM with guards.
__device__ __forceinline__ unsigned f2tf32(float f) {
    unsigned u;
    asm("cvt.rna.tf32.f32 %0, %1;" : "=r"(u) : "f"(f));
    return u;
}

__global__ __launch_bounds__(128) void gemm_tc_kernel(const float* __restrict__ A_ext,
                                                      const float* __restrict__ W,
                                                      int use_gt) {
    extern __shared__ unsigned Ws[];   // WSTRIDE * WSTRIDE tf32 words
    const float* __restrict__ A = use_gt ? (const float*)g_t : A_ext;
    int tid = threadIdx.x;

    for (int idx = tid; idx < WSTRIDE * WSTRIDE; idx += 128) {
        int k = idx / WSTRIDE, n = idx - k * WSTRIDE;
        float v = (k < DIM && n < DIM) ? W[k * DIM + n] : 0.f;
        Ws[idx] = f2tf32(v);
    }
    __syncthreads();

    int warp = tid >> 5, lane = tid & 31;
    int gid = lane >> 2;    // 0..7
    int tig = lane & 3;     // 0..3
    int m0 = blockIdx.x * 64 + warp * 16;

    float acc[NTILES][4];
    #pragma unroll
    for (int n = 0; n < NTILES; n++) {
        acc[n][0] = acc[n][1] = acc[n][2] = acc[n][3] = 0.f;
    }

    int r0 = m0 + gid;
    int r1 = m0 + gid + 8;
    bool v0 = r0 < N_NODES, v1 = r1 < N_NODES;
    const float* Ar0 = A + (size_t)r0 * DIM;
    const float* Ar1 = A + (size_t)r1 * DIM;

    for (int ks = 0; ks < KSTEPS; ks++) {
        int k0 = ks * 8;
        int c0 = k0 + tig, c1 = k0 + tig + 4;
        float f0 = (v0 && c0 < DIM) ? Ar0[c0] : 0.f;
        float f1 = (v1 && c0 < DIM) ? Ar1[c0] : 0.f;
        float f2 = (v0 && c1 < DIM) ? Ar0[c1] : 0.f;
        float f3 = (v1 && c1 < DIM) ? Ar1[c1] : 0.f;
        unsigned a0 = f2tf32(f0), a1 = f2tf32(f1), a2 = f2tf32(f2), a3 = f2tf32(f3);

        #pragma unroll
        for (int nt = 0; nt < NTILES; nt++) {
            unsigned b0 = Ws[(k0 + tig) * WSTRIDE + nt * 8 + gid];
            unsigned b1 = Ws[(k0 + tig + 4) * WSTRIDE + nt * 8 + gid];
            asm volatile(
                "mma.sync.aligned.m16n8k8.row.col.f32.tf32.tf32.f32 "
                "{%0,%1,%2,%3}, {%4,%5,%6,%7}, {%8,%9}, {%0,%1,%2,%3};"
                : "+f"(acc[nt][0]), "+f"(acc[nt][1]),
                  "+f"(acc[nt][2]), "+f"(acc[nt][3])
                : "r"(a0), "r"(a1), "r"(a2), "r"(a3), "r"(b0), "r"(b1));
        }
    }

    #pragma unroll
    for (int nt = 0; nt < NTILES; nt++) {
        int n0 = nt * 8 + tig * 2;
        if (v0) {
            if (n0 < DIM)     g_h[(size_t)r0 * DIM + n0]     = acc[nt][0];
            if (n0 + 1 < DIM) g_h[(size_t)r0 * DIM + n0 + 1] = acc[nt][1];
        }
        if (v1) {
            if (n0 < DIM)     g_h[(size_t)r1 * DIM + n0]     = acc[nt][2];
            if (n0 + 1 < DIM) g_h[(size_t)r1 * DIM + n0 + 1] = acc[nt][3];
        }
    }
}

// -------- aggregation: g_t = BN(relu(scatter(norm * g_h[src]) + b)) -----------
// one warp per destination node; zero atomics (CSR by destination)
__global__ __launch_bounds__(256) void agg_kernel(const float* __restrict__ b,
                                                  const float* __restrict__ gam,
                                                  const float* __restrict__ bet,
                                                  const float* __restrict__ rm,
                                                  const float* __restrict__ rv) {
    int warp = (blockIdx.x * blockDim.x + threadIdx.x) >> 5;
    int lane = threadIdx.x & 31;
    if (warp >= N_NODES) return;
    int node = warp;
    const float* __restrict__ h = (const float*)g_h;

    float di = g_dinv[node];
    int start = g_off[node];
    int end = (node + 1 < N_NODES) ? g_off[node + 1] : N_EDGES;

    float acc[5];
    float sw = di * di;   // self-loop weight
    const float* hn = h + (size_t)node * DIM;
    #pragma unroll
    for (int m = 0; m < 5; m++) {
        int d = lane + 32 * m;
        acc[m] = (d < DIM) ? sw * hn[d] : 0.f;
    }

    for (int j = start; j < end; j += 32) {
        int jj = j + lane;
        int rr = 0;
        float wv = 0.f;
        if (jj < end) {
            rr = g_src[jj];
            wv = g_dinv[rr];
        }
        int cnt = min(32, end - j);
        for (int l = 0; l < cnt; l++) {
            int src = __shfl_sync(0xFFFFFFFFu, rr, l);
            float w = __shfl_sync(0xFFFFFFFFu, wv, l) * di;
            const float* hr = h + (size_t)src * DIM;
            #pragma unroll
            for (int m = 0; m < 5; m++) {
                int d = lane + 32 * m;
                if (d < DIM) acc[m] = fmaf(w, hr[d], acc[m]);
            }
        }
    }

    #pragma unroll
    for (int m = 0; m < 5; m++) {
        int d = lane + 32 * m;
        if (d < DIM) {
            float v = acc[m] + b[d];
            v = fmaxf(v, 0.f);                       // ReLU
            v = (v - rm[d]) * rsqrtf(rv[d] + EPS) * gam[d] + bet[d];  // BN eval
            g_t[(size_t)node * DIM + d] = v;
        }
    }
}

// ---------------- pooling: one warp per graph, no atomics ----------------
__global__ __launch_bounds__(256) void pool_kernel(float* __restrict__ out) {
    int warp = (blockIdx.x * blockDim.x + threadIdx.x) >> 5;
    int lane = threadIdx.x & 31;
    if (warp >= N_GRAPHS) return;
    int s = g_goff[warp], e = g_goff[warp + 1];
    float acc[5] = {0.f, 0.f, 0.f, 0.f, 0.f};
    for (int n = s; n < e; n++) {
        const float* r = g_t + (size_t)n * DIM;
        #pragma unroll
        for (int m = 0; m < 5; m++) {
            int d = lane + 32 * m;
            if (d < DIM) acc[m] += r[d];
        }
    }
    float inv = 1.f / fmaxf((float)(e - s), 1.f);
    #pragma unroll
    for (int m = 0; m < 5; m++) {
        int d = lane + 32 * m;
        if (d < DIM) out[warp * DIM + d] = acc[m] * inv;
    }
}

// ---------------- launch ----------------
extern "C" void kernel_launch(void* const* d_in, const int* in_sizes, int n_in,
                              void* d_out, int out_size) {
    const float* x     = (const float*)d_in[0];
    const int*   ei    = (const int*)d_in[1];   // [2, E] int32
    const int*   batch = (const int*)d_in[2];   // [N] int32
    const float* W1 = (const float*)d_in[3];
    const float* b1 = (const float*)d_in[4];
    const float* W2 = (const float*)d_in[5];
    const float* b2 = (const float*)d_in[6];
    const float* g1 = (const float*)d_in[7];
    const float* be1 = (const float*)d_in[8];
    const float* rm1 = (const float*)d_in[9];
    const float* rv1 = (const float*)d_in[10];
    const float* g2 = (const float*)d_in[11];
    const float* be2 = (const float*)d_in[12];
    const float* rm2 = (const float*)d_in[13];
    const float* rv2 = (const float*)d_in[14];
    float* out = (float*)d_out;

    const int* row = ei;            // first E entries
    const int* col = ei + N_EDGES;  // second E entries

    const int SMEM_W = WSTRIDE * WSTRIDE * 4;   // 73984 bytes
    cudaFuncSetAttribute(gemm_tc_kernel,
                         cudaFuncAttributeMaxDynamicSharedMemorySize, SMEM_W);

    // 1. CSR build (+ per-graph ranges for pooling)
    zero_cnt_kernel<<<NB, 256>>>();
    hist_kernel<<<2048, 256>>>(col);
    reduce_kernel<<<NB, 256>>>();
    scan_bsum_kernel<<<1, 32>>>();
    scan_apply_kernel<<<NB, 256>>>();
    scatter_kernel<<<2048, 256>>>(row, col);
    goff_kernel<<<NB, 256>>>(batch);

    // 2. layer 1: tf32 GEMM -> aggregate (+bias, ReLU, BN fused)
    gemm_tc_kernel<<<(N_NODES + 63) / 64, 128, SMEM_W>>>(x, W1, 0);
    agg_kernel<<<(N_NODES * 32 + 255) / 256, 256>>>(b1, g1, be1, rm1, rv1);

    // 3. layer 2 (A comes from g_t via flag)
    gemm_tc_kernel<<<(N_NODES + 63) / 64, 128, SMEM_W>>>(x, W2, 1);
    agg_kernel<<<(N_NODES * 32 + 255) / 256, 256>>>(b2, g2, be2, rm2, rv2);

    // 4. global mean pool (sorted batch -> contiguous ranges, no atomics)
    pool_kernel<<<(N_GRAPHS * 32 + 255) / 256, 256>>>(out);
}